// round 4
// baseline (speedup 1.0000x reference)
#include <cuda_runtime.h>
#include <cuda_bf16.h>
#include <cstdint>

#define TQ    16384
#define DIN   1024
#define DOUT  1024
#define NE    8
#define BM    128
#define BN    128
#define BK    32
#define NKITER (DIN / BK)          // 32
#define MAXTILES (TQ / BM + NE)    // 136

// smem: A[2][128][36] + B[2][128][36]  (B stored [n][k], k contiguous)
#define TSTRIDE 36                                  // floats; rows 16B aligned, ldmatrix conflict-free
#define TILE_FLOATS (BM * TSTRIDE)                  // 4608
#define STAGE_FLOATS (2 * TILE_FLOATS)              // A + B
#define SMEM_BYTES (2 * STAGE_FLOATS * 4)           // 73728

// ---------------- scratch (device globals; no allocations) ----------------
__device__ int g_counts[NE];
__device__ int g_offsets[NE + 1];
__device__ int g_cursor[NE];
__device__ int g_perm[TQ];
__device__ int g_tile_expert[MAXTILES];
__device__ int g_tile_start[MAXTILES];
__device__ float g_Wt[(size_t)NE * DOUT * DIN];   // W transposed: [e][out][in]

// ---------------- binning kernels ----------------
__global__ void k_init() {
    if (threadIdx.x < NE) g_counts[threadIdx.x] = 0;
}

__global__ void k_count(const int* __restrict__ idxs) {
    __shared__ int h[NE];
    if (threadIdx.x < NE) h[threadIdx.x] = 0;
    __syncthreads();
    int t = blockIdx.x * blockDim.x + threadIdx.x;
    if (t < TQ) atomicAdd(&h[idxs[t]], 1);
    __syncthreads();
    if (threadIdx.x < NE) atomicAdd(&g_counts[threadIdx.x], h[threadIdx.x]);
}

__global__ void k_scan() {
    if (threadIdx.x == 0) {
        int off = 0;
        for (int e = 0; e < NE; e++) {
            g_offsets[e] = off;
            g_cursor[e]  = off;
            off += g_counts[e];
        }
        g_offsets[NE] = off;
        int nt = 0;
        for (int e = 0; e < NE; e++)
            for (int s = g_offsets[e]; s < g_offsets[e + 1]; s += BM) {
                g_tile_expert[nt] = e;
                g_tile_start[nt]  = s;
                nt++;
            }
        for (; nt < MAXTILES; nt++) g_tile_expert[nt] = -1;
    }
}

__global__ void k_scatter(const int* __restrict__ idxs) {
    __shared__ int lh[NE];
    __shared__ int base[NE];
    if (threadIdx.x < NE) lh[threadIdx.x] = 0;
    __syncthreads();
    int t = blockIdx.x * blockDim.x + threadIdx.x;
    int e = idxs[t];
    int r = atomicAdd(&lh[e], 1);
    __syncthreads();
    if (threadIdx.x < NE)
        base[threadIdx.x] = atomicAdd(&g_cursor[threadIdx.x], lh[threadIdx.x]);
    __syncthreads();
    g_perm[base[e] + r] = t;
}

// ---------------- W transpose: g_Wt[e][o][k] = W[e][k][o] ----------------
__global__ void k_transpose(const float* __restrict__ W) {
    __shared__ float t[32][33];
    int e = blockIdx.z;
    int k0 = blockIdx.x * 32, o0 = blockIdx.y * 32;
    const float* Ws = W + (size_t)e * DIN * DOUT;
    float* Wd = g_Wt + (size_t)e * DOUT * DIN;
    int tx = threadIdx.x, ty = threadIdx.y;   // 32 x 8
#pragma unroll
    for (int j = 0; j < 4; j++)
        t[ty + j * 8][tx] = Ws[(size_t)(k0 + ty + j * 8) * DOUT + o0 + tx];
    __syncthreads();
#pragma unroll
    for (int j = 0; j < 4; j++)
        Wd[(size_t)(o0 + ty + j * 8) * DIN + k0 + tx] = t[tx][ty + j * 8];
}

// ---------------- GEMM helpers ----------------
__device__ __forceinline__ void cp_async16(uint32_t dst, const void* src) {
    asm volatile("cp.async.cg.shared.global [%0], [%1], 16;\n" :: "r"(dst), "l"(src));
}

__device__ __forceinline__ void ldsm_x4(uint32_t r[4], uint32_t addr) {
    asm volatile("ldmatrix.sync.aligned.m8n8.x4.shared.b16 {%0,%1,%2,%3}, [%4];"
                 : "=r"(r[0]), "=r"(r[1]), "=r"(r[2]), "=r"(r[3]) : "r"(addr));
}

__device__ __forceinline__ void mma_tf32(float d[4], const uint32_t a[4], const uint32_t b[2]) {
    asm volatile(
        "mma.sync.aligned.m16n8k8.row.col.f32.tf32.tf32.f32 "
        "{%0,%1,%2,%3}, {%4,%5,%6,%7}, {%8,%9}, {%0,%1,%2,%3};\n"
        : "+f"(d[0]), "+f"(d[1]), "+f"(d[2]), "+f"(d[3])
        : "r"(a[0]), "r"(a[1]), "r"(a[2]), "r"(a[3]),
          "r"(b[0]), "r"(b[1]));
}

__device__ __forceinline__ uint32_t smem_u32(const void* p) {
    return (uint32_t)__cvta_generic_to_shared(p);
}

// ---------------- gather-GEMM: y[perm[r]] = relu(x[perm[r]] @ Wt[e]^T + b[e]) --------------
// grid=(DOUT/BN, MAXTILES): n fastest so CTAs sharing a row-tile hit L2 on gathered A rows.
__global__ __launch_bounds__(256, 2)
void k_gemm(const float* __restrict__ x, const float* __restrict__ bias,
            float* __restrict__ y)
{
    const int tile = blockIdx.y;
    const int e = g_tile_expert[tile];
    if (e < 0) return;
    const int row0 = g_tile_start[tile];
    const int row_end = g_offsets[e + 1];
    const int n0 = blockIdx.x * BN;

    extern __shared__ float smem[];
    const uint32_t sA = smem_u32(smem);                       // A stages base
    const uint32_t sB = sA + 2 * TILE_FLOATS * 4;             // B stages base (A0,A1,B0,B1)

    const int tid  = threadIdx.x;
    const int lane = tid & 31;
    const int warp = tid >> 5;
    const int warpM = warp >> 2;     // 0..1  (64-row slab)
    const int warpN = warp & 3;      // 0..3  (32-col slab)

    // ldmatrix lane decomposition: q = which 8x8 matrix, rl = row within it
    const int q  = lane >> 3;        // 0..3
    const int rl = lane & 7;         // 0..7

    // A ldmatrix per mi: matrices (q&1 -> +8 rows, q>>1 -> +4 cols)
    uint32_t aoff[4];
#pragma unroll
    for (int mi = 0; mi < 4; mi++) {
        int row = warpM * 64 + mi * 16 + (q & 1) * 8 + rl;
        aoff[mi] = (uint32_t)((row * TSTRIDE + (q >> 1) * 4) * 4);
    }
    // B ldmatrix per pair j: matrices (q&1 -> +4 cols(k), q>>1 -> +8 rows(n))
    uint32_t boff[2];
#pragma unroll
    for (int j = 0; j < 2; j++) {
        int row = warpN * 32 + 16 * j + ((q >> 1) & 1) * 8 + rl;
        boff[j] = (uint32_t)((row * TSTRIDE + (q & 1) * 4) * 4);
    }

    // gathered token per A-load chunk (row = f>>3), constant across K
    int tokv[4];
#pragma unroll
    for (int i = 0; i < 4; i++) {
        int f = i * 256 + tid;
        int gr = row0 + (f >> 3);
        tokv[i] = g_perm[(gr < row_end) ? gr : (row_end - 1)];
    }

    const float* wt = g_Wt + (size_t)(e * DOUT + n0) * DIN;
    const int cc = tid & 7;           // chunk col for this thread's loads

    auto prefetch = [&](int kt) {
        const int s = kt & 1;
        const uint32_t ab = sA + s * TILE_FLOATS * 4;
        const uint32_t bb = sB + s * TILE_FLOATS * 4;
        const int k0 = kt * BK;
#pragma unroll
        for (int i = 0; i < 4; i++) {
            int r = (i * 256 + tid) >> 3;
            cp_async16(ab + (uint32_t)(r * TSTRIDE + cc * 4) * 4,
                       x + (size_t)tokv[i] * DIN + k0 + cc * 4);
        }
#pragma unroll
        for (int i = 0; i < 4; i++) {
            int n = (i * 256 + tid) >> 3;
            cp_async16(bb + (uint32_t)(n * TSTRIDE + cc * 4) * 4,
                       wt + (size_t)n * DIN + k0 + cc * 4);
        }
        asm volatile("cp.async.commit_group;\n" ::);
    };

    float acc[4][4][4] = {};   // [mi][nj][frag]

    prefetch(0);
    for (int kt = 0; kt < NKITER; kt++) {
        const int s = kt & 1;
        asm volatile("cp.async.wait_group 0;\n" ::);
        __syncthreads();
        if (kt + 1 < NKITER) prefetch(kt + 1);

        const uint32_t ab = sA + s * TILE_FLOATS * 4;
        const uint32_t bb = sB + s * TILE_FLOATS * 4;

#pragma unroll
        for (int ks = 0; ks < BK; ks += 8) {
            uint32_t af[4][4], bp[2][4];
#pragma unroll
            for (int mi = 0; mi < 4; mi++)
                ldsm_x4(af[mi], ab + aoff[mi] + ks * 4);
#pragma unroll
            for (int j = 0; j < 2; j++)
                ldsm_x4(bp[j], bb + boff[j] + ks * 4);
            // bp[j] regs: r0=bf[2j][0], r1=bf[2j][1], r2=bf[2j+1][0], r3=bf[2j+1][1]
#pragma unroll
            for (int mi = 0; mi < 4; mi++)
#pragma unroll
                for (int nj = 0; nj < 4; nj++)
                    mma_tf32(acc[mi][nj], af[mi], &bp[nj >> 1][(nj & 1) * 2]);
        }
        __syncthreads();
    }

    // Epilogue: bias + relu + scatter store
    const int grp = lane >> 2;
    const int c4  = lane & 3;
#pragma unroll
    for (int mi = 0; mi < 4; mi++) {
#pragma unroll
        for (int h = 0; h < 2; h++) {
            int mrow = warpM * 64 + mi * 16 + grp + h * 8;
            int gr = row0 + mrow;
            if (gr >= row_end) continue;
            int tok = g_perm[gr];
#pragma unroll
            for (int nj = 0; nj < 4; nj++) {
                int n = n0 + warpN * 32 + nj * 8 + 2 * c4;
                float v0 = acc[mi][nj][h * 2 + 0] + __ldg(&bias[e * DOUT + n]);
                float v1 = acc[mi][nj][h * 2 + 1] + __ldg(&bias[e * DOUT + n + 1]);
                float2 out;
                out.x = fmaxf(v0, 0.0f);
                out.y = fmaxf(v1, 0.0f);
                *reinterpret_cast<float2*>(y + (size_t)tok * DOUT + n) = out;
            }
        }
    }
}

// ---------------- launch ----------------
extern "C" void kernel_launch(void* const* d_in, const int* in_sizes, int n_in,
                              void* d_out, int out_size) {
    const float* x    = (const float*)d_in[0];
    const int*   idxs = (const int*)  d_in[1];
    const float* W    = (const float*)d_in[2];
    const float* b    = (const float*)d_in[3];
    float* y = (float*)d_out;

    cudaFuncSetAttribute(k_gemm, cudaFuncAttributeMaxDynamicSharedMemorySize, SMEM_BYTES);

    k_init<<<1, 32>>>();
    k_count<<<TQ / 256, 256>>>(idxs);
    k_scan<<<1, 32>>>();
    k_scatter<<<TQ / 256, 256>>>(idxs);
    k_transpose<<<dim3(DIN / 32, DOUT / 32, NE), dim3(32, 8)>>>(W);

    dim3 grid(DOUT / BN, MAXTILES);
    k_gemm<<<grid, 256, SMEM_BYTES>>>(x, b, y);
}

// round 5
// speedup vs baseline: 1.4910x; 1.4910x over previous
#include <cuda_runtime.h>
#include <cuda_fp16.h>
#include <cstdint>

#define TQ    16384
#define DIN   1024
#define DOUT  1024
#define NE    8
#define BM    128
#define BN    128
#define BK    64
#define NKITER (DIN / BK)          // 16
#define MAXTILES (TQ / BM + NE)    // 136

// smem tiles in half: row = 64 halves + 8 pad = 72 halves = 144 B
#define TSTRIDE_H 72
#define TILE_HALVES (BM * TSTRIDE_H)                 // 9216
#define TILE_BYTES  (TILE_HALVES * 2)                // 18432
#define SMEM_BYTES  (4 * TILE_BYTES)                 // A0,A1,B0,B1 = 73728

// ---------------- scratch (device globals; no allocations) ----------------
__device__ int g_counts[NE];
__device__ int g_offsets[NE + 1];
__device__ int g_cursor[NE];
__device__ int g_perm[TQ];
__device__ int g_tile_expert[MAXTILES];
__device__ int g_tile_start[MAXTILES];
__device__ __half g_xh[(size_t)TQ * DIN];             // x in fp16
__device__ __half g_Wth[(size_t)NE * DOUT * DIN];     // W^T in fp16: [e][out][in]

// ---------------- binning kernels ----------------
__global__ void k_init() {
    if (threadIdx.x < NE) g_counts[threadIdx.x] = 0;
}

__global__ void k_count(const int* __restrict__ idxs) {
    __shared__ int h[NE];
    if (threadIdx.x < NE) h[threadIdx.x] = 0;
    __syncthreads();
    int t = blockIdx.x * blockDim.x + threadIdx.x;
    if (t < TQ) atomicAdd(&h[idxs[t]], 1);
    __syncthreads();
    if (threadIdx.x < NE) atomicAdd(&g_counts[threadIdx.x], h[threadIdx.x]);
}

__global__ void k_scan() {
    if (threadIdx.x == 0) {
        int off = 0;
        for (int e = 0; e < NE; e++) {
            g_offsets[e] = off;
            g_cursor[e]  = off;
            off += g_counts[e];
        }
        g_offsets[NE] = off;
        int nt = 0;
        for (int e = 0; e < NE; e++)
            for (int s = g_offsets[e]; s < g_offsets[e + 1]; s += BM) {
                g_tile_expert[nt] = e;
                g_tile_start[nt]  = s;
                nt++;
            }
        for (; nt < MAXTILES; nt++) g_tile_expert[nt] = -1;
    }
}

__global__ void k_scatter(const int* __restrict__ idxs) {
    __shared__ int lh[NE];
    __shared__ int base[NE];
    if (threadIdx.x < NE) lh[threadIdx.x] = 0;
    __syncthreads();
    int t = blockIdx.x * blockDim.x + threadIdx.x;
    int e = idxs[t];
    int r = atomicAdd(&lh[e], 1);
    __syncthreads();
    if (threadIdx.x < NE)
        base[threadIdx.x] = atomicAdd(&g_cursor[threadIdx.x], lh[threadIdx.x]);
    __syncthreads();
    g_perm[base[e] + r] = t;
}

// ---------------- x fp32 -> fp16 ----------------
__global__ void k_convert_x(const float* __restrict__ x) {
    size_t i = ((size_t)blockIdx.x * blockDim.x + threadIdx.x) * 4;
    float4 v = *reinterpret_cast<const float4*>(x + i);
    __half2 h0 = __float22half2_rn(make_float2(v.x, v.y));
    __half2 h1 = __float22half2_rn(make_float2(v.z, v.w));
    *reinterpret_cast<__half2*>(&g_xh[i])     = h0;
    *reinterpret_cast<__half2*>(&g_xh[i + 2]) = h1;
}

// ---------------- W transpose + convert: g_Wth[e][o][k] = half(W[e][k][o]) ----------------
__global__ void k_transpose(const float* __restrict__ W) {
    __shared__ float t[32][33];
    int e = blockIdx.z;
    int k0 = blockIdx.x * 32, o0 = blockIdx.y * 32;
    const float* Ws = W + (size_t)e * DIN * DOUT;
    __half* Wd = g_Wth + (size_t)e * DOUT * DIN;
    int tx = threadIdx.x, ty = threadIdx.y;   // 32 x 8
#pragma unroll
    for (int j = 0; j < 4; j++)
        t[ty + j * 8][tx] = Ws[(size_t)(k0 + ty + j * 8) * DOUT + o0 + tx];
    __syncthreads();
#pragma unroll
    for (int j = 0; j < 4; j++)
        Wd[(size_t)(o0 + ty + j * 8) * DIN + k0 + tx] = __float2half(t[tx][ty + j * 8]);
}

// ---------------- GEMM helpers ----------------
__device__ __forceinline__ void cp_async16(uint32_t dst, const void* src) {
    asm volatile("cp.async.cg.shared.global [%0], [%1], 16;\n" :: "r"(dst), "l"(src));
}

__device__ __forceinline__ void ldsm_x4(uint32_t r[4], uint32_t addr) {
    asm volatile("ldmatrix.sync.aligned.m8n8.x4.shared.b16 {%0,%1,%2,%3}, [%4];"
                 : "=r"(r[0]), "=r"(r[1]), "=r"(r[2]), "=r"(r[3]) : "r"(addr));
}

__device__ __forceinline__ void mma_f16(float d[4], const uint32_t a[4], const uint32_t b[2]) {
    asm volatile(
        "mma.sync.aligned.m16n8k16.row.col.f32.f16.f16.f32 "
        "{%0,%1,%2,%3}, {%4,%5,%6,%7}, {%8,%9}, {%0,%1,%2,%3};\n"
        : "+f"(d[0]), "+f"(d[1]), "+f"(d[2]), "+f"(d[3])
        : "r"(a[0]), "r"(a[1]), "r"(a[2]), "r"(a[3]),
          "r"(b[0]), "r"(b[1]));
}

__device__ __forceinline__ uint32_t smem_u32(const void* p) {
    return (uint32_t)__cvta_generic_to_shared(p);
}

// ---------------- gather-GEMM (fp16 inputs, fp32 accum) ----------------
// grid=(DOUT/BN, MAXTILES): n fastest so CTAs sharing a row-tile hit L2 on gathered A rows.
__global__ __launch_bounds__(256, 2)
void k_gemm(const float* __restrict__ bias, float* __restrict__ y)
{
    const int tile = blockIdx.y;
    const int e = g_tile_expert[tile];
    if (e < 0) return;
    const int row0 = g_tile_start[tile];
    const int row_end = g_offsets[e + 1];
    const int n0 = blockIdx.x * BN;

    extern __shared__ __half smem[];
    const uint32_t sA = smem_u32(smem);            // A0,A1
    const uint32_t sB = sA + 2 * TILE_BYTES;       // B0,B1

    const int tid  = threadIdx.x;
    const int lane = tid & 31;
    const int warp = tid >> 5;
    const int warpM = warp >> 2;     // 0..1  (64-row slab)
    const int warpN = warp & 3;      // 0..3  (32-col slab)

    const int q  = lane >> 3;        // ldmatrix matrix id
    const int rl = lane & 7;         // row within 8x8 matrix

    // A ldmatrix.x4 base per mi: matrices [r0-7 k0-7][r8-15 k0-7][r0-7 k8-15][r8-15 k8-15]
    uint32_t aoff[4];
#pragma unroll
    for (int mi = 0; mi < 4; mi++) {
        int row = warpM * 64 + mi * 16 + (q & 1) * 8 + rl;
        aoff[mi] = (uint32_t)(row * TSTRIDE_H + (q >> 1) * 8) * 2;
    }
    // B ldmatrix.x4 per n-16 pair j: matrices [n0-7 k0-7][n0-7 k8-15][n8-15 k0-7][n8-15 k8-15]
    uint32_t boff[2];
#pragma unroll
    for (int j = 0; j < 2; j++) {
        int row = warpN * 32 + 16 * j + (q >> 1) * 8 + rl;
        boff[j] = (uint32_t)(row * TSTRIDE_H + (q & 1) * 8) * 2;
    }

    // gathered token per A-load row (row = f>>3), constant across K
    int tokv[4];
#pragma unroll
    for (int i = 0; i < 4; i++) {
        int f = i * 256 + tid;
        int gr = row0 + (f >> 3);
        tokv[i] = g_perm[(gr < row_end) ? gr : (row_end - 1)];
    }

    const __half* wt = g_Wth + (size_t)(e * DOUT + n0) * DIN;
    const int cc = tid & 7;           // 16B chunk col (8 halves each)

    auto prefetch = [&](int kt) {
        const int s = kt & 1;
        const uint32_t ab = sA + s * TILE_BYTES;
        const uint32_t bb = sB + s * TILE_BYTES;
        const int k0 = kt * BK;
#pragma unroll
        for (int i = 0; i < 4; i++) {
            int r = (i * 256 + tid) >> 3;
            cp_async16(ab + (uint32_t)(r * TSTRIDE_H + cc * 8) * 2,
                       g_xh + (size_t)tokv[i] * DIN + k0 + cc * 8);
        }
#pragma unroll
        for (int i = 0; i < 4; i++) {
            int n = (i * 256 + tid) >> 3;
            cp_async16(bb + (uint32_t)(n * TSTRIDE_H + cc * 8) * 2,
                       wt + (size_t)n * DIN + k0 + cc * 8);
        }
        asm volatile("cp.async.commit_group;\n" ::);
    };

    float acc[4][4][4] = {};   // [mi][nj][frag]

    prefetch(0);
    for (int kt = 0; kt < NKITER; kt++) {
        const int s = kt & 1;
        asm volatile("cp.async.wait_group 0;\n" ::);
        __syncthreads();
        if (kt + 1 < NKITER) prefetch(kt + 1);

        const uint32_t ab = sA + s * TILE_BYTES;
        const uint32_t bb = sB + s * TILE_BYTES;

#pragma unroll
        for (int ks = 0; ks < BK; ks += 16) {
            uint32_t af[4][4], bp[2][4];
#pragma unroll
            for (int mi = 0; mi < 4; mi++)
                ldsm_x4(af[mi], ab + aoff[mi] + ks * 2);
#pragma unroll
            for (int j = 0; j < 2; j++)
                ldsm_x4(bp[j], bb + boff[j] + ks * 2);
            // bp[j]: r0,r1 = B frag for n-octet 2j; r2,r3 = for n-octet 2j+1
#pragma unroll
            for (int mi = 0; mi < 4; mi++)
#pragma unroll
                for (int nj = 0; nj < 4; nj++)
                    mma_f16(acc[mi][nj], af[mi], &bp[nj >> 1][(nj & 1) * 2]);
        }
        __syncthreads();
    }

    // Epilogue: bias + relu + scatter store
    const int grp = lane >> 2;
    const int c4  = lane & 3;
#pragma unroll
    for (int mi = 0; mi < 4; mi++) {
#pragma unroll
        for (int h = 0; h < 2; h++) {
            int mrow = warpM * 64 + mi * 16 + grp + h * 8;
            int gr = row0 + mrow;
            if (gr >= row_end) continue;
            int tok = g_perm[gr];
#pragma unroll
            for (int nj = 0; nj < 4; nj++) {
                int n = n0 + warpN * 32 + nj * 8 + 2 * c4;
                float v0 = acc[mi][nj][h * 2 + 0] + __ldg(&bias[e * DOUT + n]);
                float v1 = acc[mi][nj][h * 2 + 1] + __ldg(&bias[e * DOUT + n + 1]);
                float2 out;
                out.x = fmaxf(v0, 0.0f);
                out.y = fmaxf(v1, 0.0f);
                *reinterpret_cast<float2*>(y + (size_t)tok * DOUT + n) = out;
            }
        }
    }
}

// ---------------- launch ----------------
extern "C" void kernel_launch(void* const* d_in, const int* in_sizes, int n_in,
                              void* d_out, int out_size) {
    const float* x    = (const float*)d_in[0];
    const int*   idxs = (const int*)  d_in[1];
    const float* W    = (const float*)d_in[2];
    const float* b    = (const float*)d_in[3];
    float* y = (float*)d_out;

    cudaFuncSetAttribute(k_gemm, cudaFuncAttributeMaxDynamicSharedMemorySize, SMEM_BYTES);

    k_init<<<1, 32>>>();
    k_count<<<TQ / 256, 256>>>(idxs);
    k_scan<<<1, 32>>>();
    k_scatter<<<TQ / 256, 256>>>(idxs);
    k_convert_x<<<(TQ * DIN / 4) / 256, 256>>>(x);
    k_transpose<<<dim3(DIN / 32, DOUT / 32, NE), dim3(32, 8)>>>(W);

    dim3 grid(DOUT / BN, MAXTILES);
    k_gemm<<<grid, 256, SMEM_BYTES>>>(b, y);
}

// round 6
// speedup vs baseline: 1.5484x; 1.0385x over previous
#include <cuda_runtime.h>
#include <cuda_fp16.h>
#include <cstdint>

#define TQ    16384
#define DIN   1024
#define DOUT  1024
#define NE    8
#define BM    128
#define BN    128
#define BK    64
#define NKITER (DIN / BK)          // 16
#define MAXTILES (TQ / BM + NE)    // 136
#define NSTAGE 3

// smem tiles in half: row = 64 halves + 8 pad = 72 halves = 144 B
#define TSTRIDE_H 72
#define TILE_HALVES (BM * TSTRIDE_H)                 // 9216
#define TILE_BYTES  (TILE_HALVES * 2)                // 18432
#define STAGE_BYTES (2 * TILE_BYTES)                 // A + B = 36864
#define SMEM_BYTES  (NSTAGE * STAGE_BYTES)           // 110592

// ---------------- scratch (device globals; no allocations) ----------------
__device__ int g_counts[NE];
__device__ int g_offsets[NE + 1];
__device__ int g_cursor[NE];
__device__ int g_perm[TQ];
__device__ int g_tile_expert[MAXTILES];
__device__ int g_tile_start[MAXTILES];
__device__ __half g_xh[(size_t)TQ * DIN];             // x in fp16, PERMUTED (packed by expert)
__device__ __half g_Wth[(size_t)NE * DOUT * DIN];     // W^T in fp16: [e][out][in]

// ---------------- binning kernels ----------------
__global__ void k_init() {
    if (threadIdx.x < NE) g_counts[threadIdx.x] = 0;
}

__global__ void k_count(const int* __restrict__ idxs) {
    __shared__ int h[NE];
    if (threadIdx.x < NE) h[threadIdx.x] = 0;
    __syncthreads();
    int t = blockIdx.x * blockDim.x + threadIdx.x;
    if (t < TQ) atomicAdd(&h[idxs[t]], 1);
    __syncthreads();
    if (threadIdx.x < NE) atomicAdd(&g_counts[threadIdx.x], h[threadIdx.x]);
}

__global__ void k_scan() {
    if (threadIdx.x == 0) {
        int off = 0;
        for (int e = 0; e < NE; e++) {
            g_offsets[e] = off;
            g_cursor[e]  = off;
            off += g_counts[e];
        }
        g_offsets[NE] = off;
        int nt = 0;
        for (int e = 0; e < NE; e++)
            for (int s = g_offsets[e]; s < g_offsets[e + 1]; s += BM) {
                g_tile_expert[nt] = e;
                g_tile_start[nt]  = s;
                nt++;
            }
        for (; nt < MAXTILES; nt++) g_tile_expert[nt] = -1;
    }
}

__global__ void k_scatter(const int* __restrict__ idxs) {
    __shared__ int lh[NE];
    __shared__ int base[NE];
    if (threadIdx.x < NE) lh[threadIdx.x] = 0;
    __syncthreads();
    int t = blockIdx.x * blockDim.x + threadIdx.x;
    int e = idxs[t];
    int r = atomicAdd(&lh[e], 1);
    __syncthreads();
    if (threadIdx.x < NE)
        base[threadIdx.x] = atomicAdd(&g_cursor[threadIdx.x], lh[threadIdx.x]);
    __syncthreads();
    g_perm[base[e] + r] = t;
}

// ---------------- prep: gathered x->fp16 pack  +  W transpose->fp16 ----------------
// blocks [0, TQ):            g_xh[p][:] = half(x[g_perm[p]][:])
// blocks [TQ, TQ + 8*1024):  g_Wth[e][o][k] = half(W[e][k][o])
__global__ void k_prep(const float* __restrict__ x, const float* __restrict__ W) {
    const int tid = threadIdx.x;
    if (blockIdx.x < TQ) {
        int p = blockIdx.x;
        int tok = g_perm[p];
        float4 v = *reinterpret_cast<const float4*>(x + (size_t)tok * DIN + tid * 4);
        __half2 h0 = __float22half2_rn(make_float2(v.x, v.y));
        __half2 h1 = __float22half2_rn(make_float2(v.z, v.w));
        __half* dst = g_xh + (size_t)p * DIN + tid * 4;
        *reinterpret_cast<__half2*>(dst)     = h0;
        *reinterpret_cast<__half2*>(dst + 2) = h1;
    } else {
        __shared__ float t[32][33];
        int bid = blockIdx.x - TQ;
        int e = bid >> 10;
        int rem = bid & 1023;
        int k0 = (rem >> 5) * 32, o0 = (rem & 31) * 32;
        const float* Ws = W + (size_t)e * DIN * DOUT;
        __half* Wd = g_Wth + (size_t)e * DOUT * DIN;
        int tx = tid & 31, ty = tid >> 5;   // 32 x 8
#pragma unroll
        for (int j = 0; j < 4; j++)
            t[ty + j * 8][tx] = Ws[(size_t)(k0 + ty + j * 8) * DOUT + o0 + tx];
        __syncthreads();
#pragma unroll
        for (int j = 0; j < 4; j++)
            Wd[(size_t)(o0 + ty + j * 8) * DIN + k0 + tx] = __float2half(t[tx][ty + j * 8]);
    }
}

// ---------------- GEMM helpers ----------------
__device__ __forceinline__ void cp_async16(uint32_t dst, const void* src) {
    asm volatile("cp.async.cg.shared.global [%0], [%1], 16;\n" :: "r"(dst), "l"(src));
}

__device__ __forceinline__ void ldsm_x4(uint32_t r[4], uint32_t addr) {
    asm volatile("ldmatrix.sync.aligned.m8n8.x4.shared.b16 {%0,%1,%2,%3}, [%4];"
                 : "=r"(r[0]), "=r"(r[1]), "=r"(r[2]), "=r"(r[3]) : "r"(addr));
}

__device__ __forceinline__ void mma_f16(float d[4], const uint32_t a[4], const uint32_t b[2]) {
    asm volatile(
        "mma.sync.aligned.m16n8k16.row.col.f32.f16.f16.f32 "
        "{%0,%1,%2,%3}, {%4,%5,%6,%7}, {%8,%9}, {%0,%1,%2,%3};\n"
        : "+f"(d[0]), "+f"(d[1]), "+f"(d[2]), "+f"(d[3])
        : "r"(a[0]), "r"(a[1]), "r"(a[2]), "r"(a[3]),
          "r"(b[0]), "r"(b[1]));
}

__device__ __forceinline__ uint32_t smem_u32(const void* p) {
    return (uint32_t)__cvta_generic_to_shared(p);
}

// ---------------- gather-GEMM (fp16 inputs, fp32 accum), A pre-packed ----------------
// grid=(DOUT/BN, MAXTILES): n fastest so CTAs sharing a row-tile hit L2 on packed A rows.
__global__ __launch_bounds__(256, 2)
void k_gemm(const float* __restrict__ bias, float* __restrict__ y)
{
    const int tile = blockIdx.y;
    const int e = g_tile_expert[tile];
    if (e < 0) return;
    const int row0 = g_tile_start[tile];
    const int row_end = g_offsets[e + 1];
    const int n0 = blockIdx.x * BN;

    extern __shared__ __half smem[];
    const uint32_t sbase = smem_u32(smem);

    const int tid  = threadIdx.x;
    const int lane = tid & 31;
    const int warp = tid >> 5;
    const int warpM = warp >> 2;     // 0..1  (64-row slab)
    const int warpN = warp & 3;      // 0..3  (32-col slab)

    const int q  = lane >> 3;        // ldmatrix matrix id
    const int rl = lane & 7;         // row within 8x8 matrix

    uint32_t aoff[4];
#pragma unroll
    for (int mi = 0; mi < 4; mi++) {
        int row = warpM * 64 + mi * 16 + (q & 1) * 8 + rl;
        aoff[mi] = (uint32_t)(row * TSTRIDE_H + (q >> 1) * 8) * 2;
    }
    uint32_t boff[2];
#pragma unroll
    for (int j = 0; j < 2; j++) {
        int row = warpN * 32 + 16 * j + (q >> 1) * 8 + rl;
        boff[j] = (uint32_t)(row * TSTRIDE_H + (q & 1) * 8) * 2 + TILE_BYTES;
    }

    // A rows are packed: row0 + r (clamped to stay in-bounds; garbage rows masked at store)
    const __half* xa = g_xh;
    const __half* wt = g_Wth + (size_t)(e * DOUT + n0) * DIN;
    const int cc = tid & 7;           // 16B chunk col (8 halves each)

    int arow[4];
#pragma unroll
    for (int i = 0; i < 4; i++) {
        int r = (i * 256 + tid) >> 3;
        int gr = row0 + r;
        arow[i] = (gr < TQ) ? gr : (TQ - 1);
    }

    auto prefetch = [&](int kt) {
        const uint32_t st = sbase + (kt % NSTAGE) * STAGE_BYTES;
        const int k0 = kt * BK;
#pragma unroll
        for (int i = 0; i < 4; i++) {
            int r = (i * 256 + tid) >> 3;
            cp_async16(st + (uint32_t)(r * TSTRIDE_H + cc * 8) * 2,
                       xa + (size_t)arow[i] * DIN + k0 + cc * 8);
        }
#pragma unroll
        for (int i = 0; i < 4; i++) {
            int n = (i * 256 + tid) >> 3;
            cp_async16(st + TILE_BYTES + (uint32_t)(n * TSTRIDE_H + cc * 8) * 2,
                       wt + (size_t)n * DIN + k0 + cc * 8);
        }
        asm volatile("cp.async.commit_group;\n" ::);
    };

    float acc[4][4][4] = {};   // [mi][nj][frag]

    prefetch(0);
    prefetch(1);

    for (int kt = 0; kt < NKITER; kt++) {
        if (kt < NKITER - 1) {
            asm volatile("cp.async.wait_group 1;\n" ::);
        } else {
            asm volatile("cp.async.wait_group 0;\n" ::);
        }
        __syncthreads();
        if (kt + 2 < NKITER) prefetch(kt + 2);

        const uint32_t st = sbase + (kt % NSTAGE) * STAGE_BYTES;

#pragma unroll
        for (int ks = 0; ks < BK; ks += 16) {
            uint32_t af[4][4], bp[2][4];
#pragma unroll
            for (int mi = 0; mi < 4; mi++)
                ldsm_x4(af[mi], st + aoff[mi] + ks * 2);
#pragma unroll
            for (int j = 0; j < 2; j++)
                ldsm_x4(bp[j], st + boff[j] + ks * 2);
#pragma unroll
            for (int mi = 0; mi < 4; mi++)
#pragma unroll
                for (int nj = 0; nj < 4; nj++)
                    mma_f16(acc[mi][nj], af[mi], &bp[nj >> 1][(nj & 1) * 2]);
        }
    }

    // Epilogue: bias + relu + scatter store (perm only here)
    const int grp = lane >> 2;
    const int c4  = lane & 3;
#pragma unroll
    for (int mi = 0; mi < 4; mi++) {
#pragma unroll
        for (int h = 0; h < 2; h++) {
            int mrow = warpM * 64 + mi * 16 + grp + h * 8;
            int gr = row0 + mrow;
            if (gr >= row_end) continue;
            int tok = g_perm[gr];
#pragma unroll
            for (int nj = 0; nj < 4; nj++) {
                int n = n0 + warpN * 32 + nj * 8 + 2 * c4;
                float v0 = acc[mi][nj][h * 2 + 0] + __ldg(&bias[e * DOUT + n]);
                float v1 = acc[mi][nj][h * 2 + 1] + __ldg(&bias[e * DOUT + n + 1]);
                float2 out;
                out.x = fmaxf(v0, 0.0f);
                out.y = fmaxf(v1, 0.0f);
                *reinterpret_cast<float2*>(y + (size_t)tok * DOUT + n) = out;
            }
        }
    }
}

// ---------------- launch ----------------
extern "C" void kernel_launch(void* const* d_in, const int* in_sizes, int n_in,
                              void* d_out, int out_size) {
    const float* x    = (const float*)d_in[0];
    const int*   idxs = (const int*)  d_in[1];
    const float* W    = (const float*)d_in[2];
    const float* b    = (const float*)d_in[3];
    float* y = (float*)d_out;

    cudaFuncSetAttribute(k_gemm, cudaFuncAttributeMaxDynamicSharedMemorySize, SMEM_BYTES);

    k_init<<<1, 32>>>();
    k_count<<<TQ / 256, 256>>>(idxs);
    k_scan<<<1, 32>>>();
    k_scatter<<<TQ / 256, 256>>>(idxs);
    k_prep<<<TQ + NE * (DIN / 32) * (DOUT / 32), 256>>>(x, W);

    dim3 grid(DOUT / BN, MAXTILES);
    k_gemm<<<grid, 256, SMEM_BYTES>>>(b, y);
}